// round 3
// baseline (speedup 1.0000x reference)
#include <cuda_runtime.h>
#include <math.h>

#define BB 8
#define NPTS 2048
#define NTHREADS 512
#define ROWS_PER_WARP 8
#define ROWS_PER_CTA 128          // 16 warps * 8 rows
#define CHUNKS 16                 // 2048 / 128

// eps = 0.005
#define KLOG 288.53900817779268f          // log2(e)/eps
#define EPSLN2 0.0034657359027997266f     // eps*ln2  (= 1/KLOG)
#define ACONST (-0.038123094930796993f)   // eps*log(1/N) = -0.005*ln(2048)

__device__ __forceinline__ float ex2f(float x) {
    float r;
    asm("ex2.approx.ftz.f32 %0, %1;" : "=f"(r) : "f"(x));
    return r;
}

// Persistent scratch (static device arrays: allowed; cudaMalloc is not)
__device__ float g_f[BB * NPTS];
__device__ float g_g[BB * NPTS];
__device__ float g_partial[BB * CHUNKS];

__global__ void init_kernel() {
    int i = blockIdx.x * blockDim.x + threadIdx.x;
    if (i < BB * NPTS) g_g[i] = 0.0f;
}

// One Sinkhorn half-step.
// dir == 0 : f-update  (rows = pcs1, cols = pcs2, colPot = g, out = f)
// dir == 1 : g-update  (rows = pcs2, cols = pcs1, colPot = f, out = g)
__global__ __launch_bounds__(NTHREADS, 1)
void sink_half(const float* __restrict__ rowPts,
               const float* __restrict__ colPts,
               int dir)
{
    __shared__ float4 sCol[NPTS];   // (y0, y1, y2, h)  32 KB

    const int b   = blockIdx.y;
    const int tid = threadIdx.x;

    const float* colPot = dir ? g_f : g_g;
    float*       outPot = dir ? g_g : g_f;

    // Build column table: h_j = (pot_j - ||y_j||^2) * K
    const float* cp = colPts + b * NPTS * 3;
    const float* gp = colPot + b * NPTS;
    for (int j = tid; j < NPTS; j += NTHREADS) {
        float y0 = cp[3 * j], y1 = cp[3 * j + 1], y2 = cp[3 * j + 2];
        float yy = y0 * y0 + y1 * y1 + y2 * y2;
        sCol[j] = make_float4(y0, y1, y2, (gp[j] - yy) * KLOG);
    }
    __syncthreads();

    const int warp = tid >> 5, lane = tid & 31;
    const int row0 = blockIdx.x * ROWS_PER_CTA + warp * ROWS_PER_WARP;
    const float* rp = rowPts + b * NPTS * 3;

    float X0[8], X1[8], X2[8], xx[8], m[8], S[8];
    #pragma unroll
    for (int r = 0; r < 8; r++) {
        int i = row0 + r;
        float x0 = rp[3 * i], x1 = rp[3 * i + 1], x2 = rp[3 * i + 2];
        xx[r] = x0 * x0 + x1 * x1 + x2 * x2;
        X0[r] = 2.0f * KLOG * x0;
        X1[r] = 2.0f * KLOG * x1;
        X2[r] = 2.0f * KLOG * x2;
        m[r]  = -1e30f;
    }

    // Phase A: row maxima of w' = h_j + X.y
    for (int j = lane; j < NPTS; j += 32) {
        float4 c = sCol[j];
        #pragma unroll
        for (int r = 0; r < 8; r++) {
            float w = fmaf(X0[r], c.x, fmaf(X1[r], c.y, fmaf(X2[r], c.z, c.w)));
            m[r] = fmaxf(m[r], w);
        }
    }
    #pragma unroll
    for (int r = 0; r < 8; r++) {
        #pragma unroll
        for (int o = 16; o; o >>= 1)
            m[r] = fmaxf(m[r], __shfl_xor_sync(0xffffffffu, m[r], o));
        S[r] = 0.0f;
    }

    // Phase B: sum of 2^(w' - m)
    for (int j = lane; j < NPTS; j += 32) {
        float4 c = sCol[j];
        #pragma unroll
        for (int r = 0; r < 8; r++) {
            float w = fmaf(X0[r], c.x, fmaf(X1[r], c.y, fmaf(X2[r], c.z, c.w)));
            S[r] += ex2f(w - m[r]);
        }
    }
    #pragma unroll
    for (int r = 0; r < 8; r++) {
        #pragma unroll
        for (int o = 16; o; o >>= 1)
            S[r] += __shfl_xor_sync(0xffffffffu, S[r], o);
    }

    if (lane == 0) {
        #pragma unroll
        for (int r = 0; r < 8; r++) {
            // f_i = ACONST - EPSLN2*(m + log2 S) + xx
            float val = ACONST - EPSLN2 * (m[r] + __log2f(S[r])) + xx[r];
            outPot[b * NPTS + row0 + r] = val;
        }
    }
}

// dist_i = N * sum_j 2^((f_i + g_j - C_ij)*K) * C_ij ; emit per-CTA sum of sqrt(dist)
__global__ __launch_bounds__(NTHREADS, 1)
void dist_kernel(const float* __restrict__ pcs1,
                 const float* __restrict__ pcs2)
{
    __shared__ float4 sCol[NPTS];
    __shared__ float  sYY[NPTS];
    __shared__ float  wsum[16];

    const int b   = blockIdx.y;
    const int tid = threadIdx.x;

    const float* cp = pcs2 + b * NPTS * 3;
    for (int j = tid; j < NPTS; j += NTHREADS) {
        float y0 = cp[3 * j], y1 = cp[3 * j + 1], y2 = cp[3 * j + 2];
        float yy = y0 * y0 + y1 * y1 + y2 * y2;
        sYY[j] = yy;
        sCol[j] = make_float4(y0, y1, y2, (g_g[b * NPTS + j] - yy) * KLOG);
    }
    __syncthreads();

    const int warp = tid >> 5, lane = tid & 31;
    const int row0 = blockIdx.x * ROWS_PER_CTA + warp * ROWS_PER_WARP;
    const float* rp = pcs1 + b * NPTS * 3;

    float X0[8], X1[8], X2[8], xx[8], cr[8], acc[8];
    #pragma unroll
    for (int r = 0; r < 8; r++) {
        int i = row0 + r;
        float x0 = rp[3 * i], x1 = rp[3 * i + 1], x2 = rp[3 * i + 2];
        xx[r] = x0 * x0 + x1 * x1 + x2 * x2;
        X0[r] = 2.0f * KLOG * x0;
        X1[r] = 2.0f * KLOG * x1;
        X2[r] = 2.0f * KLOG * x2;
        cr[r] = (g_f[b * NPTS + i] - xx[r]) * KLOG;
        acc[r] = 0.0f;
    }

    for (int j = lane; j < NPTS; j += 32) {
        float4 c = sCol[j];
        float yy = sYY[j];
        #pragma unroll
        for (int r = 0; r < 8; r++) {
            float t = fmaf(X0[r], c.x, fmaf(X1[r], c.y, X2[r] * c.z)); // 2K*(x.y)
            float p = ex2f(t + c.w + cr[r]);                           // 2^logP (logP <= ~0)
            float C = fmaf(-EPSLN2, t, xx[r] + yy);                    // xx+yy-2x.y
            acc[r] = fmaf(p, C, acc[r]);
        }
    }
    #pragma unroll
    for (int r = 0; r < 8; r++) {
        #pragma unroll
        for (int o = 16; o; o >>= 1)
            acc[r] += __shfl_xor_sync(0xffffffffu, acc[r], o);
    }

    if (lane == 0) {
        float s = 0.0f;
        #pragma unroll
        for (int r = 0; r < 8; r++)
            s += sqrtf(fmaxf(acc[r] * (float)NPTS, 0.0f));
        wsum[warp] = s;
    }
    __syncthreads();
    if (tid == 0) {
        float s = 0.0f;
        #pragma unroll
        for (int w = 0; w < 16; w++) s += wsum[w];
        g_partial[b * CHUNKS + blockIdx.x] = s;
    }
}

__global__ void final_kernel(float* __restrict__ out) {
    __shared__ float s[BB * CHUNKS];
    int tid = threadIdx.x;
    s[tid] = g_partial[tid];
    __syncthreads();
    for (int o = (BB * CHUNKS) / 2; o; o >>= 1) {
        if (tid < o) s[tid] += s[tid + o];
        __syncthreads();
    }
    if (tid == 0) out[0] = s[0] * (1.0f / (BB * NPTS));
}

extern "C" void kernel_launch(void* const* d_in, const int* in_sizes, int n_in,
                              void* d_out, int out_size)
{
    const float* pcs1 = (const float*)d_in[0];
    const float* pcs2 = (const float*)d_in[1];
    float* out = (float*)d_out;

    init_kernel<<<(BB * NPTS + NTHREADS - 1) / NTHREADS, NTHREADS>>>();

    dim3 grid(CHUNKS, BB);
    for (int it = 0; it < 50; it++) {
        sink_half<<<grid, NTHREADS>>>(pcs1, pcs2, 0);   // f = F(g)
        sink_half<<<grid, NTHREADS>>>(pcs2, pcs1, 1);   // g = G(f)
    }
    sink_half<<<grid, NTHREADS>>>(pcs1, pcs2, 0);       // final f = F(g)

    dist_kernel<<<grid, NTHREADS>>>(pcs1, pcs2);
    final_kernel<<<1, BB * CHUNKS>>>(out);
}

// round 4
// speedup vs baseline: 1.0717x; 1.0717x over previous
#include <cuda_runtime.h>
#include <math.h>

#define BB 8
#define NPTS 2048
#define NPAIR 1024
#define NTHREADS 512
#define ROWS_PER_WARP 8
#define ROWS_PER_CTA 128          // 16 warps * 8 rows
#define CHUNKS 16                 // 2048 / 128

// eps = 0.005
#define KLOG 288.53900817779268f          // log2(e)/eps
#define EPSLN2 0.0034657359027997266f     // eps*ln2  (= 1/KLOG)
#define ACONST (-0.038123094930796993f)   // eps*log(1/N) = -0.005*ln(2048)

typedef unsigned long long u64;

__device__ __forceinline__ float ex2f(float x) {
    float r;
    asm("ex2.approx.ftz.f32 %0, %1;" : "=f"(r) : "f"(x));
    return r;
}
__device__ __forceinline__ u64 pack2(float lo, float hi) {
    u64 r; asm("mov.b64 %0, {%1, %2};" : "=l"(r) : "f"(lo), "f"(hi)); return r;
}
__device__ __forceinline__ void unpack2(u64 v, float& lo, float& hi) {
    asm("mov.b64 {%0, %1}, %2;" : "=f"(lo), "=f"(hi) : "l"(v));
}
__device__ __forceinline__ u64 fma2(u64 a, u64 b, u64 c) {
    u64 r; asm("fma.rn.f32x2 %0, %1, %2, %3;" : "=l"(r) : "l"(a), "l"(b), "l"(c)); return r;
}
__device__ __forceinline__ u64 add2(u64 a, u64 b) {
    u64 r; asm("add.rn.f32x2 %0, %1, %2;" : "=l"(r) : "l"(a), "l"(b)); return r;
}

// Persistent scratch (static device arrays: allowed; cudaMalloc is not)
__device__ float g_f[BB * NPTS];
__device__ float g_g[BB * NPTS];
__device__ float g_partial[BB * CHUNKS];

__global__ void init_kernel() {
    int i = blockIdx.x * blockDim.x + threadIdx.x;
    if (i < BB * NPTS) g_g[i] = 0.0f;
}

// One Sinkhorn half-step, f32x2-packed along the column (j) dimension.
// dir == 0 : f-update  (rows = pcs1, cols = pcs2, colPot = g, out = f)
// dir == 1 : g-update  (rows = pcs2, cols = pcs1, colPot = f, out = g)
__global__ __launch_bounds__(NTHREADS, 1)
void sink_half(const float* __restrict__ rowPts,
               const float* __restrict__ colPts,
               int dir)
{
    // Pair-interleaved column tables:
    //   sA[p] = (y0_{2p}, y0_{2p+1}, y1_{2p}, y1_{2p+1})
    //   sB[p] = (y2_{2p}, y2_{2p+1}, h_{2p},  h_{2p+1})
    __shared__ float4 sA[NPAIR];   // 16 KB
    __shared__ float4 sB[NPAIR];   // 16 KB

    const int b   = blockIdx.y;
    const int tid = threadIdx.x;

    const float* colPot = dir ? g_f : g_g;
    float*       outPot = dir ? g_g : g_f;

    const float* cp = colPts + b * NPTS * 3;
    const float* gp = colPot + b * NPTS;
    for (int p = tid; p < NPAIR; p += NTHREADS) {
        int j = 2 * p;
        float a0 = cp[3*j],   a1 = cp[3*j+1], a2 = cp[3*j+2];
        float b0 = cp[3*j+3], b1 = cp[3*j+4], b2 = cp[3*j+5];
        float ha = (gp[j]   - (a0*a0 + a1*a1 + a2*a2)) * KLOG;
        float hb = (gp[j+1] - (b0*b0 + b1*b1 + b2*b2)) * KLOG;
        sA[p] = make_float4(a0, b0, a1, b1);
        sB[p] = make_float4(a2, b2, ha, hb);
    }
    __syncthreads();

    const int warp = tid >> 5, lane = tid & 31;
    const int row0 = blockIdx.x * ROWS_PER_CTA + warp * ROWS_PER_WARP;
    const float* rp = rowPts + b * NPTS * 3;

    u64 X0b[8], X1b[8], X2b[8];
    float xx[8], m[8];
    #pragma unroll
    for (int r = 0; r < 8; r++) {
        int i = row0 + r;
        float x0 = rp[3*i], x1 = rp[3*i+1], x2 = rp[3*i+2];
        xx[r] = x0*x0 + x1*x1 + x2*x2;
        X0b[r] = pack2(2.0f*KLOG*x0, 2.0f*KLOG*x0);
        X1b[r] = pack2(2.0f*KLOG*x1, 2.0f*KLOG*x1);
        X2b[r] = pack2(2.0f*KLOG*x2, 2.0f*KLOG*x2);
        m[r]  = -1e30f;
    }

    unsigned int aA0 = (unsigned int)__cvta_generic_to_shared(sA) + lane * 16u;
    unsigned int aB0 = (unsigned int)__cvta_generic_to_shared(sB) + lane * 16u;

    // Phase A: row maxima of w' = h_j + X.y   (packed pairs of j)
    {
        unsigned int aA = aA0, aB = aB0;
        #pragma unroll 2
        for (int it = 0; it < NPAIR / 32; it++) {
            u64 y0p, y1p, y2p, hp;
            asm("ld.shared.v2.b64 {%0, %1}, [%2];" : "=l"(y0p), "=l"(y1p) : "r"(aA));
            asm("ld.shared.v2.b64 {%0, %1}, [%2];" : "=l"(y2p), "=l"(hp)  : "r"(aB));
            #pragma unroll
            for (int r = 0; r < 8; r++) {
                u64 w = fma2(X0b[r], y0p, fma2(X1b[r], y1p, fma2(X2b[r], y2p, hp)));
                float wl, wh; unpack2(w, wl, wh);
                m[r] = fmaxf(m[r], fmaxf(wl, wh));
            }
            aA += 32u * 16u; aB += 32u * 16u;
        }
    }

    u64 mnegb[8], Sp[8];
    #pragma unroll
    for (int r = 0; r < 8; r++) {
        #pragma unroll
        for (int o = 16; o; o >>= 1)
            m[r] = fmaxf(m[r], __shfl_xor_sync(0xffffffffu, m[r], o));
        mnegb[r] = pack2(-m[r], -m[r]);
        Sp[r] = 0ull;
    }

    // Phase B: sum of 2^(w' - m)   (packed pairs of j)
    {
        unsigned int aA = aA0, aB = aB0;
        #pragma unroll 2
        for (int it = 0; it < NPAIR / 32; it++) {
            u64 y0p, y1p, y2p, hp;
            asm("ld.shared.v2.b64 {%0, %1}, [%2];" : "=l"(y0p), "=l"(y1p) : "r"(aA));
            asm("ld.shared.v2.b64 {%0, %1}, [%2];" : "=l"(y2p), "=l"(hp)  : "r"(aB));
            #pragma unroll
            for (int r = 0; r < 8; r++) {
                u64 w = fma2(X0b[r], y0p, fma2(X1b[r], y1p, fma2(X2b[r], y2p, hp)));
                u64 t = add2(w, mnegb[r]);
                float tl, th; unpack2(t, tl, th);
                Sp[r] = add2(Sp[r], pack2(ex2f(tl), ex2f(th)));
            }
            aA += 32u * 16u; aB += 32u * 16u;
        }
    }

    if (1) {
        float S[8];
        #pragma unroll
        for (int r = 0; r < 8; r++) {
            float sl, sh; unpack2(Sp[r], sl, sh);
            S[r] = sl + sh;
            #pragma unroll
            for (int o = 16; o; o >>= 1)
                S[r] += __shfl_xor_sync(0xffffffffu, S[r], o);
        }
        if (lane == 0) {
            #pragma unroll
            for (int r = 0; r < 8; r++) {
                float val = ACONST - EPSLN2 * (m[r] + __log2f(S[r])) + xx[r];
                outPot[b * NPTS + row0 + r] = val;
            }
        }
    }
}

// dist_i = N * sum_j 2^((f_i + g_j - C_ij)*K) * C_ij ; emit per-CTA sum of sqrt(dist)
__global__ __launch_bounds__(NTHREADS, 1)
void dist_kernel(const float* __restrict__ pcs1,
                 const float* __restrict__ pcs2)
{
    __shared__ float4 sCol[NPTS];
    __shared__ float  sYY[NPTS];
    __shared__ float  wsum[16];

    const int b   = blockIdx.y;
    const int tid = threadIdx.x;

    const float* cp = pcs2 + b * NPTS * 3;
    for (int j = tid; j < NPTS; j += NTHREADS) {
        float y0 = cp[3*j], y1 = cp[3*j+1], y2 = cp[3*j+2];
        float yy = y0*y0 + y1*y1 + y2*y2;
        sYY[j] = yy;
        sCol[j] = make_float4(y0, y1, y2, (g_g[b * NPTS + j] - yy) * KLOG);
    }
    __syncthreads();

    const int warp = tid >> 5, lane = tid & 31;
    const int row0 = blockIdx.x * ROWS_PER_CTA + warp * ROWS_PER_WARP;
    const float* rp = pcs1 + b * NPTS * 3;

    float X0[8], X1[8], X2[8], xx[8], cr[8], acc[8];
    #pragma unroll
    for (int r = 0; r < 8; r++) {
        int i = row0 + r;
        float x0 = rp[3*i], x1 = rp[3*i+1], x2 = rp[3*i+2];
        xx[r] = x0*x0 + x1*x1 + x2*x2;
        X0[r] = 2.0f*KLOG*x0;
        X1[r] = 2.0f*KLOG*x1;
        X2[r] = 2.0f*KLOG*x2;
        cr[r] = (g_f[b * NPTS + i] - xx[r]) * KLOG;
        acc[r] = 0.0f;
    }

    for (int j = lane; j < NPTS; j += 32) {
        float4 c = sCol[j];
        float yy = sYY[j];
        #pragma unroll
        for (int r = 0; r < 8; r++) {
            float t = fmaf(X0[r], c.x, fmaf(X1[r], c.y, X2[r] * c.z)); // 2K*(x.y)
            float p = ex2f(t + c.w + cr[r]);                           // 2^logP (logP <= ~0)
            float C = fmaf(-EPSLN2, t, xx[r] + yy);                    // xx+yy-2x.y
            acc[r] = fmaf(p, C, acc[r]);
        }
    }
    #pragma unroll
    for (int r = 0; r < 8; r++) {
        #pragma unroll
        for (int o = 16; o; o >>= 1)
            acc[r] += __shfl_xor_sync(0xffffffffu, acc[r], o);
    }

    if (lane == 0) {
        float s = 0.0f;
        #pragma unroll
        for (int r = 0; r < 8; r++)
            s += sqrtf(fmaxf(acc[r] * (float)NPTS, 0.0f));
        wsum[warp] = s;
    }
    __syncthreads();
    if (tid == 0) {
        float s = 0.0f;
        #pragma unroll
        for (int w = 0; w < 16; w++) s += wsum[w];
        g_partial[b * CHUNKS + blockIdx.x] = s;
    }
}

__global__ void final_kernel(float* __restrict__ out) {
    __shared__ float s[BB * CHUNKS];
    int tid = threadIdx.x;
    s[tid] = g_partial[tid];
    __syncthreads();
    for (int o = (BB * CHUNKS) / 2; o; o >>= 1) {
        if (tid < o) s[tid] += s[tid + o];
        __syncthreads();
    }
    if (tid == 0) out[0] = s[0] * (1.0f / (BB * NPTS));
}

extern "C" void kernel_launch(void* const* d_in, const int* in_sizes, int n_in,
                              void* d_out, int out_size)
{
    const float* pcs1 = (const float*)d_in[0];
    const float* pcs2 = (const float*)d_in[1];
    float* out = (float*)d_out;

    init_kernel<<<(BB * NPTS + NTHREADS - 1) / NTHREADS, NTHREADS>>>();

    dim3 grid(CHUNKS, BB);
    for (int it = 0; it < 50; it++) {
        sink_half<<<grid, NTHREADS>>>(pcs1, pcs2, 0);   // f = F(g)
        sink_half<<<grid, NTHREADS>>>(pcs2, pcs1, 1);   // g = G(f)
    }
    sink_half<<<grid, NTHREADS>>>(pcs1, pcs2, 0);       // final f = F(g)

    dist_kernel<<<grid, NTHREADS>>>(pcs1, pcs2);
    final_kernel<<<1, BB * CHUNKS>>>(out);
}

// round 5
// speedup vs baseline: 1.2579x; 1.1738x over previous
#include <cuda_runtime.h>
#include <math.h>

#define BB 8
#define NPTS 2048
#define NPAIR 1024
#define NTHREADS 512
#define ROWS_PER_CTA 128          // 16 warps * 8 rows
#define CHUNKS 16                 // 2048 / 128

// eps = 0.005
#define KLOG 288.53900817779268f          // log2(e)/eps
#define EPSLN2 0.0034657359027997266f     // eps*ln2  (= 1/KLOG)
#define ACONST (-0.038123094930796993f)   // eps*log(1/N)
#define SKIP_THR (-40.0f)                 // skip pairs with w-mp below this

typedef unsigned long long u64;

__device__ __forceinline__ float ex2f(float x) {
    float r;
    asm("ex2.approx.ftz.f32 %0, %1;" : "=f"(r) : "f"(x));
    return r;
}
__device__ __forceinline__ u64 pack2(float lo, float hi) {
    u64 r; asm("mov.b64 %0, {%1, %2};" : "=l"(r) : "f"(lo), "f"(hi)); return r;
}
__device__ __forceinline__ void unpack2(u64 v, float& lo, float& hi) {
    asm("mov.b64 {%0, %1}, %2;" : "=f"(lo), "=f"(hi) : "l"(v));
}
__device__ __forceinline__ u64 fma2(u64 a, u64 b, u64 c) {
    u64 r; asm("fma.rn.f32x2 %0, %1, %2, %3;" : "=l"(r) : "l"(a), "l"(b), "l"(c)); return r;
}
__device__ __forceinline__ u64 add2(u64 a, u64 b) {
    u64 r; asm("add.rn.f32x2 %0, %1, %2;" : "=l"(r) : "l"(a), "l"(b)); return r;
}

// Persistent scratch (device globals: allowed; cudaMalloc is not)
__device__ float g_p1[BB * NPTS * 3];   // Morton-sorted pcs1
__device__ float g_p2[BB * NPTS * 3];   // Morton-sorted pcs2
__device__ float g_f[BB * NPTS];
__device__ float g_g[BB * NPTS];
__device__ float g_mf[BB * NPTS];       // prev row-max for f-updates
__device__ float g_mg[BB * NPTS];       // prev row-max for g-updates
__device__ float g_partial[BB * CHUNKS];

__global__ void init_kernel() {
    int i = blockIdx.x * blockDim.x + threadIdx.x;
    if (i < BB * NPTS) g_g[i] = 0.0f;
}

__device__ __forceinline__ unsigned expand_bits(unsigned v) {
    v &= 0x3FFu;
    v = (v | (v << 16)) & 0x030000FFu;
    v = (v | (v << 8))  & 0x0300F00Fu;
    v = (v | (v << 4))  & 0x030C30C3u;
    v = (v | (v << 2))  & 0x09249249u;
    return v;
}

// One CTA per batch: Morton-key bitonic sort, write gathered points to globals.
__global__ __launch_bounds__(NTHREADS, 1)
void sort_kernel(const float* __restrict__ pts, int side)
{
    __shared__ unsigned key[NPTS];
    __shared__ int      idx[NPTS];
    const int b = blockIdx.x, tid = threadIdx.x;
    const float* p = pts + b * NPTS * 3;

    for (int j = tid; j < NPTS; j += NTHREADS) {
        float x = p[3*j], y = p[3*j+1], z = p[3*j+2];
        unsigned qx = (unsigned)fminf(fmaxf(x * 1024.0f, 0.0f), 1023.0f);
        unsigned qy = (unsigned)fminf(fmaxf(y * 1024.0f, 0.0f), 1023.0f);
        unsigned qz = (unsigned)fminf(fmaxf(z * 1024.0f, 0.0f), 1023.0f);
        key[j] = expand_bits(qx) | (expand_bits(qy) << 1) | (expand_bits(qz) << 2);
        idx[j] = j;
    }
    __syncthreads();

    for (int k2 = 2; k2 <= NPTS; k2 <<= 1) {
        for (int j2 = k2 >> 1; j2 > 0; j2 >>= 1) {
            for (int i = tid; i < NPTS; i += NTHREADS) {
                int l = i ^ j2;
                if (l > i) {
                    bool up = ((i & k2) == 0);
                    unsigned ki = key[i], kl = key[l];
                    bool swp = up ? (ki > kl) : (ki < kl);
                    if (swp) {
                        key[i] = kl; key[l] = ki;
                        int t = idx[i]; idx[i] = idx[l]; idx[l] = t;
                    }
                }
            }
            __syncthreads();
        }
    }

    float* out = (side ? g_p2 : g_p1) + b * NPTS * 3;
    for (int k = tid; k < NPTS; k += NTHREADS) {
        int s = idx[k];
        out[3*k]   = p[3*s];
        out[3*k+1] = p[3*s+1];
        out[3*k+2] = p[3*s+2];
    }
}

// ---------- Warmup: rigorous two-pass half-step (also emits row max) ----------
__global__ __launch_bounds__(NTHREADS, 1)
void sink_warm(int dir)
{
    __shared__ float4 sA[NPAIR];
    __shared__ float4 sB[NPAIR];

    const int b = blockIdx.y, tid = threadIdx.x;
    const float* rowPts = dir ? g_p2 : g_p1;
    const float* colPts = dir ? g_p1 : g_p2;
    const float* colPot = dir ? g_f  : g_g;
    float*       outPot = dir ? g_g  : g_f;
    float*       outM   = dir ? g_mg : g_mf;

    const float* cp = colPts + b * NPTS * 3;
    const float* gp = colPot + b * NPTS;
    for (int p = tid; p < NPAIR; p += NTHREADS) {
        int j = 2 * p;
        float a0 = cp[3*j],   a1 = cp[3*j+1], a2 = cp[3*j+2];
        float b0 = cp[3*j+3], b1 = cp[3*j+4], b2 = cp[3*j+5];
        float ha = (gp[j]   - (a0*a0 + a1*a1 + a2*a2)) * KLOG;
        float hb = (gp[j+1] - (b0*b0 + b1*b1 + b2*b2)) * KLOG;
        sA[p] = make_float4(a0, b0, a1, b1);
        sB[p] = make_float4(a2, b2, ha, hb);
    }
    __syncthreads();

    const int warp = tid >> 5, lane = tid & 31;
    const int row0 = blockIdx.x * ROWS_PER_CTA + warp * 8;
    const float* rp = rowPts + b * NPTS * 3;

    u64 X0b[8], X1b[8], X2b[8];
    float xx[8], m[8];
    #pragma unroll
    for (int r = 0; r < 8; r++) {
        int i = row0 + r;
        float x0 = rp[3*i], x1 = rp[3*i+1], x2 = rp[3*i+2];
        xx[r] = x0*x0 + x1*x1 + x2*x2;
        X0b[r] = pack2(2.0f*KLOG*x0, 2.0f*KLOG*x0);
        X1b[r] = pack2(2.0f*KLOG*x1, 2.0f*KLOG*x1);
        X2b[r] = pack2(2.0f*KLOG*x2, 2.0f*KLOG*x2);
        m[r]  = -1e30f;
    }

    unsigned int aA0 = (unsigned int)__cvta_generic_to_shared(sA) + lane * 16u;
    unsigned int aB0 = (unsigned int)__cvta_generic_to_shared(sB) + lane * 16u;

    {
        unsigned int aA = aA0, aB = aB0;
        #pragma unroll 2
        for (int it = 0; it < NPAIR / 32; it++) {
            u64 y0p, y1p, y2p, hp;
            asm("ld.shared.v2.b64 {%0, %1}, [%2];" : "=l"(y0p), "=l"(y1p) : "r"(aA));
            asm("ld.shared.v2.b64 {%0, %1}, [%2];" : "=l"(y2p), "=l"(hp)  : "r"(aB));
            #pragma unroll
            for (int r = 0; r < 8; r++) {
                u64 w = fma2(X0b[r], y0p, fma2(X1b[r], y1p, fma2(X2b[r], y2p, hp)));
                float wl, wh; unpack2(w, wl, wh);
                m[r] = fmaxf(m[r], fmaxf(wl, wh));
            }
            aA += 512u; aB += 512u;
        }
    }

    u64 mnegb[8], Sp[8];
    #pragma unroll
    for (int r = 0; r < 8; r++) {
        #pragma unroll
        for (int o = 16; o; o >>= 1)
            m[r] = fmaxf(m[r], __shfl_xor_sync(0xffffffffu, m[r], o));
        mnegb[r] = pack2(-m[r], -m[r]);
        Sp[r] = 0ull;
    }

    {
        unsigned int aA = aA0, aB = aB0;
        #pragma unroll 2
        for (int it = 0; it < NPAIR / 32; it++) {
            u64 y0p, y1p, y2p, hp;
            asm("ld.shared.v2.b64 {%0, %1}, [%2];" : "=l"(y0p), "=l"(y1p) : "r"(aA));
            asm("ld.shared.v2.b64 {%0, %1}, [%2];" : "=l"(y2p), "=l"(hp)  : "r"(aB));
            #pragma unroll
            for (int r = 0; r < 8; r++) {
                u64 w = fma2(X0b[r], y0p, fma2(X1b[r], y1p, fma2(X2b[r], y2p, hp)));
                u64 t = add2(w, mnegb[r]);
                float tl, th; unpack2(t, tl, th);
                Sp[r] = add2(Sp[r], pack2(ex2f(tl), ex2f(th)));
            }
            aA += 512u; aB += 512u;
        }
    }

    float S[8];
    #pragma unroll
    for (int r = 0; r < 8; r++) {
        float sl, sh; unpack2(Sp[r], sl, sh);
        S[r] = sl + sh;
        #pragma unroll
        for (int o = 16; o; o >>= 1)
            S[r] += __shfl_xor_sync(0xffffffffu, S[r], o);
    }
    if (lane == 0) {
        #pragma unroll
        for (int r = 0; r < 8; r++) {
            outPot[b * NPTS + row0 + r] = ACONST - EPSLN2 * (m[r] + __log2f(S[r])) + xx[r];
            outM[b * NPTS + row0 + r]   = m[r];
        }
    }
}

// ---------- Fast: single-pass half-step with carried max + chunk skip ----------
__global__ __launch_bounds__(NTHREADS, 1)
void sink_fast(int dir)
{
    __shared__ float4 sA[NPAIR];
    __shared__ float4 sB[NPAIR];

    const int b = blockIdx.y, tid = threadIdx.x;
    const float* rowPts = dir ? g_p2 : g_p1;
    const float* colPts = dir ? g_p1 : g_p2;
    const float* colPot = dir ? g_f  : g_g;
    float*       outPot = dir ? g_g  : g_f;
    float*       mArr   = dir ? g_mg : g_mf;

    const float* cp = colPts + b * NPTS * 3;
    const float* gp = colPot + b * NPTS;
    for (int p = tid; p < NPAIR; p += NTHREADS) {
        int j = 2 * p;
        float a0 = cp[3*j],   a1 = cp[3*j+1], a2 = cp[3*j+2];
        float b0 = cp[3*j+3], b1 = cp[3*j+4], b2 = cp[3*j+5];
        float ha = (gp[j]   - (a0*a0 + a1*a1 + a2*a2)) * KLOG;
        float hb = (gp[j+1] - (b0*b0 + b1*b1 + b2*b2)) * KLOG;
        sA[p] = make_float4(a0, b0, a1, b1);
        sB[p] = make_float4(a2, b2, ha, hb);
    }
    __syncthreads();

    const int warp = tid >> 5, lane = tid & 31;
    const int row0 = blockIdx.x * ROWS_PER_CTA + warp * 8;
    const float* rp = rowPts + b * NPTS * 3;

    u64 X0b[8], X1b[8], X2b[8], negMb[8], Sp[8];
    float mrun[8];
    #pragma unroll
    for (int r = 0; r < 8; r++) {
        int i = row0 + r;
        float x0 = rp[3*i], x1 = rp[3*i+1], x2 = rp[3*i+2];
        X0b[r] = pack2(2.0f*KLOG*x0, 2.0f*KLOG*x0);
        X1b[r] = pack2(2.0f*KLOG*x1, 2.0f*KLOG*x1);
        X2b[r] = pack2(2.0f*KLOG*x2, 2.0f*KLOG*x2);
        float mp = mArr[b * NPTS + i];
        negMb[r] = pack2(-mp, -mp);
        mrun[r] = -1e30f;
        Sp[r] = 0ull;
    }

    unsigned int aA = (unsigned int)__cvta_generic_to_shared(sA) + lane * 16u;
    unsigned int aB = (unsigned int)__cvta_generic_to_shared(sB) + lane * 16u;

    for (int it = 0; it < NPAIR / 32; it++) {
        u64 y0p, y1p, y2p, hp;
        asm("ld.shared.v2.b64 {%0, %1}, [%2];" : "=l"(y0p), "=l"(y1p) : "r"(aA));
        asm("ld.shared.v2.b64 {%0, %1}, [%2];" : "=l"(y2p), "=l"(hp)  : "r"(aB));

        u64 w[8];
        float chunkAcc = -1e30f;
        #pragma unroll
        for (int r = 0; r < 8; r++) {
            u64 hpr = add2(hp, negMb[r]);                 // fold -mp into bias
            w[r] = fma2(X0b[r], y0p, fma2(X1b[r], y1p, fma2(X2b[r], y2p, hpr)));
            float wl, wh; unpack2(w[r], wl, wh);
            float pm = fmaxf(wl, wh);
            mrun[r] = fmaxf(mrun[r], pm);
            chunkAcc = fmaxf(chunkAcc, pm);
        }
        if (__ballot_sync(0xffffffffu, chunkAcc > SKIP_THR)) {
            #pragma unroll
            for (int r = 0; r < 8; r++) {
                float wl, wh; unpack2(w[r], wl, wh);
                Sp[r] = add2(Sp[r], pack2(ex2f(wl), ex2f(wh)));
            }
        }
        aA += 512u; aB += 512u;
    }

    float S[8];
    #pragma unroll
    for (int r = 0; r < 8; r++) {
        float sl, sh; unpack2(Sp[r], sl, sh);
        S[r] = sl + sh;
        #pragma unroll
        for (int o = 16; o; o >>= 1) {
            S[r]    += __shfl_xor_sync(0xffffffffu, S[r], o);
            mrun[r]  = fmaxf(mrun[r], __shfl_xor_sync(0xffffffffu, mrun[r], o));
        }
    }
    if (lane == 0) {
        #pragma unroll
        for (int r = 0; r < 8; r++) {
            int i = row0 + r;
            float x0 = rp[3*i], x1 = rp[3*i+1], x2 = rp[3*i+2];
            float xx = x0*x0 + x1*x1 + x2*x2;
            float mp_lo, mp_hi; unpack2(negMb[r], mp_lo, mp_hi);
            float mp = -mp_lo;
            float Sv = fmaxf(S[r], 1e-38f);
            outPot[b * NPTS + i] = ACONST - EPSLN2 * (mp + __log2f(Sv)) + xx;
            mArr[b * NPTS + i]   = mp + mrun[r];          // true max this iter
        }
    }
}

// dist_i = N * sum_j 2^((f_i + g_j - C_ij)*K) * C_ij ; per-CTA sum of sqrt(dist)
__global__ __launch_bounds__(NTHREADS, 1)
void dist_kernel()
{
    __shared__ float4 sCol[NPTS];
    __shared__ float  sYY[NPTS];
    __shared__ float  wsum[16];

    const int b = blockIdx.y, tid = threadIdx.x;

    const float* cp = g_p2 + b * NPTS * 3;
    for (int j = tid; j < NPTS; j += NTHREADS) {
        float y0 = cp[3*j], y1 = cp[3*j+1], y2 = cp[3*j+2];
        float yy = y0*y0 + y1*y1 + y2*y2;
        sYY[j] = yy;
        sCol[j] = make_float4(y0, y1, y2, (g_g[b * NPTS + j] - yy) * KLOG);
    }
    __syncthreads();

    const int warp = tid >> 5, lane = tid & 31;
    const int row0 = blockIdx.x * ROWS_PER_CTA + warp * 8;
    const float* rp = g_p1 + b * NPTS * 3;

    float X0[8], X1[8], X2[8], xx[8], cr[8], acc[8];
    #pragma unroll
    for (int r = 0; r < 8; r++) {
        int i = row0 + r;
        float x0 = rp[3*i], x1 = rp[3*i+1], x2 = rp[3*i+2];
        xx[r] = x0*x0 + x1*x1 + x2*x2;
        X0[r] = 2.0f*KLOG*x0;
        X1[r] = 2.0f*KLOG*x1;
        X2[r] = 2.0f*KLOG*x2;
        cr[r] = (g_f[b * NPTS + i] - xx[r]) * KLOG;
        acc[r] = 0.0f;
    }

    for (int j = lane; j < NPTS; j += 32) {
        float4 c = sCol[j];
        float yy = sYY[j];
        #pragma unroll
        for (int r = 0; r < 8; r++) {
            float t = fmaf(X0[r], c.x, fmaf(X1[r], c.y, X2[r] * c.z));
            float p = ex2f(t + c.w + cr[r]);
            float C = fmaf(-EPSLN2, t, xx[r] + yy);
            acc[r] = fmaf(p, C, acc[r]);
        }
    }
    #pragma unroll
    for (int r = 0; r < 8; r++) {
        #pragma unroll
        for (int o = 16; o; o >>= 1)
            acc[r] += __shfl_xor_sync(0xffffffffu, acc[r], o);
    }

    if (lane == 0) {
        float s = 0.0f;
        #pragma unroll
        for (int r = 0; r < 8; r++)
            s += sqrtf(fmaxf(acc[r] * (float)NPTS, 0.0f));
        wsum[warp] = s;
    }
    __syncthreads();
    if (tid == 0) {
        float s = 0.0f;
        #pragma unroll
        for (int w = 0; w < 16; w++) s += wsum[w];
        g_partial[b * CHUNKS + blockIdx.x] = s;
    }
}

__global__ void final_kernel(float* __restrict__ out) {
    __shared__ float s[BB * CHUNKS];
    int tid = threadIdx.x;
    s[tid] = g_partial[tid];
    __syncthreads();
    for (int o = (BB * CHUNKS) / 2; o; o >>= 1) {
        if (tid < o) s[tid] += s[tid + o];
        __syncthreads();
    }
    if (tid == 0) out[0] = s[0] * (1.0f / (BB * NPTS));
}

extern "C" void kernel_launch(void* const* d_in, const int* in_sizes, int n_in,
                              void* d_out, int out_size)
{
    const float* pcs1 = (const float*)d_in[0];
    const float* pcs2 = (const float*)d_in[1];
    float* out = (float*)d_out;

    init_kernel<<<(BB * NPTS + NTHREADS - 1) / NTHREADS, NTHREADS>>>();
    sort_kernel<<<BB, NTHREADS>>>(pcs1, 0);
    sort_kernel<<<BB, NTHREADS>>>(pcs2, 1);

    dim3 grid(CHUNKS, BB);
    // 2 warmup iterations: rigorous two-pass, populates m arrays
    for (int it = 0; it < 2; it++) {
        sink_warm<<<grid, NTHREADS>>>(0);
        sink_warm<<<grid, NTHREADS>>>(1);
    }
    // 48 fast iterations
    for (int it = 2; it < 50; it++) {
        sink_fast<<<grid, NTHREADS>>>(0);
        sink_fast<<<grid, NTHREADS>>>(1);
    }
    sink_fast<<<grid, NTHREADS>>>(0);   // final f-update

    dist_kernel<<<grid, NTHREADS>>>();
    final_kernel<<<1, BB * CHUNKS>>>(out);
}